// round 13
// baseline (speedup 1.0000x reference)
#include <cuda_runtime.h>
#include <cstddef>

#define NB    16
#define HH    512
#define WWID  512
#define NPB   20000
#define NPTS  (NB * NPB)          // 320000
#define EPSV  1e-5f
#define NBLK  1250                // NPTS / 256 exactly
#define NROWS (NB * HH)           // 8192 row bins

// ---------------- scratch ----------------
__device__ int g_map[NB * HH * WWID + 8];      // pos+1 encoding; 0 = empty
__device__ int g_rowcnt[NROWS];                // row histogram (zeroed by fc tail)
__device__ int g_rowctr[NROWS];                // placement cursors (zeroed by fc tail)
__device__ int g_rowbase[NROWS];               // exclusive prefix
__device__ int g_src[NPTS];                    // pos -> (i | b<<24)
__device__ int g_nbr[9 * NPTS];                // pos-space tap list: (npos<<4 | tap)
__device__ int g_cntv[NPTS];
__device__ int g_maskv[NPTS];                  // 9-bit tap mask
__device__ __align__(16) float g_y1[NPTS * 8];
__device__ __align__(16) float g_y2[NPTS * 16];
__device__ __align__(16) float g_y3[NPTS * 32];
__device__ double g_part[NBLK * 64];           // [sum(C) | sumsq(C)] rows, stride 64
__device__ float g_bn1[16], g_bn2[32], g_bn3[64];
__device__ unsigned g_pool[NB * 32];
__device__ unsigned g_ctr[4];

#define LAST_BLOCK_GATE(ctr, target, lastvar)                        \
    __threadfence();                                                 \
    __syncthreads();                                                 \
    if (threadIdx.x == 0)                                            \
        lastvar = (atomicAdd(&(ctr), 1u) == (unsigned)(target) - 1u);\
    __syncthreads();

// ---------------- gated-last-block BN fold (double partials) ----------------
template <int C>
__device__ __forceinline__ void fold_bn(const float* __restrict__ gamma,
                                        const float* __restrict__ beta,
                                        float* __restrict__ bn) {
    __shared__ double s4[4][64];
    int c = threadIdx.x & 63, seg = threadIdx.x >> 6;
    double a = 0.0;
    if (c < 2 * C && seg < 4)
        for (int r = seg; r < NBLK; r += 4) a += __ldcg(&g_part[r * 64 + c]);
    if (seg < 4) s4[seg][c] = a;
    __syncthreads();
    if ((int)threadIdx.x < C) {
        int c0 = threadIdx.x;
        double S = s4[0][c0] + s4[1][c0] + s4[2][c0] + s4[3][c0];
        double Q = s4[0][C + c0] + s4[1][C + c0] + s4[2][C + c0] + s4[3][C + c0];
        double m = S / (double)NPTS;
        double var = Q / (double)NPTS - m * m;
        float sc = gamma[c0] * rsqrtf((float)var + EPSV);
        bn[c0] = sc;
        bn[C + c0] = beta[c0] - (float)m * sc;
    }
}

// ---------------- block stats (double): acc[NCH] -> g_part row ----------------
template <int NCH>
__device__ __forceinline__ void block_stats(const float* acc, int blk) {
    __shared__ double s_red[8][2 * NCH];
    int lane = threadIdx.x & 31, warp = threadIdx.x >> 5;
#pragma unroll
    for (int co = 0; co < NCH; co++) {
        double s = (double)acc[co], q = (double)acc[co] * (double)acc[co];
#pragma unroll
        for (int off = 16; off; off >>= 1) {
            s += __shfl_down_sync(0xffffffffu, s, off);
            q += __shfl_down_sync(0xffffffffu, q, off);
        }
        if (lane == 0) { s_red[warp][co] = s; s_red[warp][NCH + co] = q; }
    }
    __syncthreads();
    if (threadIdx.x < 2 * NCH) {
        double t = 0.0;
#pragma unroll
        for (int w = 0; w < 8; w++) t += s_red[w][threadIdx.x];
        g_part[blk * 64 + threadIdx.x] = t;
    }
}

// ---------------- deterministic block-local sort by 9-bit mask (256 pts) ----------
__device__ __forceinline__ void sort_by_mask(int key, unsigned char* wcnt /*8*512*/,
                                             short* tot, short* bb, short* s_ord) {
    int warp = threadIdx.x >> 5, lane = threadIdx.x & 31;
    for (int t = threadIdx.x; t < 8 * 512 / 4; t += 256)
        reinterpret_cast<unsigned*>(wcnt)[t] = 0u;
    __syncthreads();
    unsigned mymask = __match_any_sync(0xffffffffu, key);
    int lrank = __popc(mymask & ((1u << lane) - 1u));
    if (lane == (__ffs(mymask) - 1))
        wcnt[warp * 512 + key] = (unsigned char)__popc(mymask);
    __syncthreads();
    for (int k = threadIdx.x; k < 512; k += 256) {
        int run = 0;
#pragma unroll
        for (int w = 0; w < 8; w++) {
            int c = wcnt[w * 512 + k];
            wcnt[w * 512 + k] = (unsigned char)run;
            run += c;
        }
        tot[k] = (short)run;
    }
    __syncthreads();
    if (threadIdx.x < 32) {
        int l = threadIdx.x;
        int s = 0;
#pragma unroll
        for (int q = 0; q < 16; q++) { bb[l * 16 + q] = (short)s; s += tot[l * 16 + q]; }
        int chunk = s, off = chunk;
#pragma unroll
        for (int d = 1; d < 32; d <<= 1) {
            int n = __shfl_up_sync(0xffffffffu, off, d);
            if (l >= d) off += n;
        }
        off -= chunk;
#pragma unroll
        for (int q = 0; q < 16; q++) bb[l * 16 + q] = (short)(bb[l * 16 + q] + off);
    }
    __syncthreads();
    s_ord[bb[key] + wcnt[warp * 512 + key] + lrank] = (short)threadIdx.x;
    __syncthreads();
}

// ---------------- 1: row histogram; last block scans -> g_rowbase ----------------
__global__ __launch_bounds__(256)
void k_hist(const int* __restrict__ idx) {
    __shared__ bool s_last;
    int i = blockIdx.x * 256 + threadIdx.x;
    int b = idx[3 * i], y = idx[3 * i + 1];
    atomicAdd(&g_rowcnt[(b << 9) | y], 1);

    LAST_BLOCK_GATE(g_ctr[0], NBLK, s_last);
    if (!s_last) return;

    int t = threadIdx.x;
    int loc[32]; int run = 0;
#pragma unroll
    for (int k = 0; k < 32; k++) { loc[k] = run; run += __ldcg(&g_rowcnt[t * 32 + k]); }
    int lane = t & 31, w = t >> 5;
    int v = run;
#pragma unroll
    for (int d = 1; d < 32; d <<= 1) {
        int n = __shfl_up_sync(0xffffffffu, v, d);
        if (lane >= d) v += n;
    }
    __shared__ int wsum[8];
    if (lane == 31) wsum[w] = v;
    __syncthreads();
    int wo = 0;
    for (int k = 0; k < w; k++) wo += wsum[k];
    int excl = wo + v - run;
#pragma unroll
    for (int k = 0; k < 32; k++) g_rowbase[t * 32 + k] = excl + loc[k];
}

// ---------------- 2: place points in spatial order; map stores pos+1 --------------
__global__ __launch_bounds__(256)
void k_place(const int* __restrict__ idx) {
    int i = blockIdx.x * 256 + threadIdx.x;
    int b = idx[3 * i], y = idx[3 * i + 1], x = idx[3 * i + 2];
    int bin = (b << 9) | y;
    int pos = g_rowbase[bin] + atomicAdd(&g_rowctr[bin], 1);
    g_map[(b << 18) | (y << 9) | x] = pos + 1;
    g_src[pos] = i | (b << 24);
}

// ---------------- 3: probe + conv1 + pos-space tap list + stats; gated BN1 --------
__global__ __launch_bounds__(256)
void k_build(const int* __restrict__ idx, const float* __restrict__ feats,
             const float* __restrict__ w1,
             const float* __restrict__ g1, const float* __restrict__ b1)
{
    __shared__ float ws[72];
    __shared__ bool s_last;
    if (threadIdx.x < 72) ws[threadIdx.x] = w1[threadIdx.x];
    __syncthreads();

    int pos = blockIdx.x * 256 + threadIdx.x;
    int sv = g_src[pos];
    int i = sv & 0xFFFFFF, b = sv >> 24;
    int y = idx[3 * i + 1], x = idx[3 * i + 2];
    int base = b << 18;

    int np[9];
#pragma unroll
    for (int t = 0; t < 9; t++) {
        int ny = y + t / 3 - 1, nx = x + t % 3 - 1;
        bool ok = ((unsigned)ny < (unsigned)HH) && ((unsigned)nx < (unsigned)WWID);
        int nyc = ok ? ny : y, nxc = ok ? nx : x;
        int mv = g_map[base + (nyc << 9) + nxc];
        np[t] = ok ? (mv - 1) : -1;
    }

    float acc[8];
#pragma unroll
    for (int c = 0; c < 8; c++) acc[c] = 0.f;
    int cnt = 0, mask = 0;
#pragma unroll
    for (int t = 0; t < 9; t++) {
        if (np[t] >= 0) {
            g_nbr[cnt * NPTS + pos] = (np[t] << 4) | t;
            cnt++;
            mask |= (1 << t);
            float v = feats[g_src[np[t]] & 0xFFFFFF];
#pragma unroll
            for (int co = 0; co < 8; co++)
                acc[co] = fmaf(v, ws[t * 8 + co], acc[co]);
        }
    }
    g_cntv[pos] = cnt;
    g_maskv[pos] = mask;

    float4* orow = reinterpret_cast<float4*>(g_y1 + (size_t)pos * 8);
    orow[0] = make_float4(acc[0], acc[1], acc[2], acc[3]);
    orow[1] = make_float4(acc[4], acc[5], acc[6], acc[7]);

    block_stats<8>(acc, blockIdx.x);
    LAST_BLOCK_GATE(g_ctr[1], NBLK, s_last);
    if (s_last) fold_bn<8>(g1, b1, g_bn1);
}

// ---------------- 4: conv2 (8->16), mask-sorted warps, local gathers --------------
__global__ __launch_bounds__(256, 4)
void k_conv2(const float* __restrict__ w2,
             const float* __restrict__ g2, const float* __restrict__ b2)
{
    __shared__ float s_ws[9 * 132];
    __shared__ float s_ab[32];
    __shared__ unsigned char s_wcnt[8 * 512];
    __shared__ short s_tot[512], s_bb[512], s_ord[256];
    __shared__ bool s_last;
    for (int t = threadIdx.x; t < 9 * 128; t += 256)
        s_ws[(t >> 7) * 132 + (t & 127)] = w2[t];
    if (threadIdx.x < 16) s_ab[threadIdx.x] = g_bn1[threadIdx.x];

    int p0 = blockIdx.x * 256 + threadIdx.x;
    int key = g_maskv[p0];
    sort_by_mask(key, s_wcnt, s_tot, s_bb, s_ord);

    int pos = blockIdx.x * 256 + s_ord[threadIdx.x];
    int cnt = g_cntv[pos];

    float acc[16];
#pragma unroll
    for (int c = 0; c < 16; c++) acc[c] = 0.f;

    for (int s = 0; s < cnt; s++) {
        int p = g_nbr[s * NPTS + pos];
        int j = p >> 4, tap = p & 15;
        const float4* inr = reinterpret_cast<const float4*>(g_y1 + (size_t)j * 8);
        float4 r0 = inr[0], r1 = inr[1];          // L1-local gather
        const float* wr = s_ws + tap * 132;       // warp-uniform (mask-sorted)
        float vv[8] = {r0.x, r0.y, r0.z, r0.w, r1.x, r1.y, r1.z, r1.w};
#pragma unroll
        for (int ci = 0; ci < 8; ci++) {
            float v = fmaxf(fmaf(vv[ci], s_ab[ci], s_ab[8 + ci]), 0.f);
#pragma unroll
            for (int co = 0; co < 16; co++)
                acc[co] = fmaf(v, wr[ci * 16 + co], acc[co]);
        }
    }

    float4* orow = reinterpret_cast<float4*>(g_y2 + (size_t)pos * 16);
#pragma unroll
    for (int c4 = 0; c4 < 4; c4++)
        orow[c4] = make_float4(acc[4 * c4], acc[4 * c4 + 1], acc[4 * c4 + 2], acc[4 * c4 + 3]);

    block_stats<16>(acc, blockIdx.x);
    LAST_BLOCK_GATE(g_ctr[2], NBLK, s_last);
    if (s_last) fold_bn<16>(g2, b2, g_bn2);
}

// ---------------- 5: conv3 (16->32), mask-sorted warps, local gathers -------------
__global__ __launch_bounds__(256, 3)
void k_conv3(const float* __restrict__ w3,
             const float* __restrict__ g3, const float* __restrict__ b3)
{
    __shared__ float s_ws[9 * 516];
    __shared__ float s_ab[32];
    __shared__ unsigned char s_wcnt[8 * 512];
    __shared__ short s_tot[512], s_bb[512], s_ord[256];
    __shared__ bool s_last;
    for (int t = threadIdx.x; t < 9 * 512; t += 256)
        s_ws[(t >> 9) * 516 + (t & 511)] = w3[t];
    if (threadIdx.x < 32) s_ab[threadIdx.x] = g_bn2[threadIdx.x];

    int p0 = blockIdx.x * 256 + threadIdx.x;
    int key = g_maskv[p0];
    sort_by_mask(key, s_wcnt, s_tot, s_bb, s_ord);

    int pos = blockIdx.x * 256 + s_ord[threadIdx.x];
    int cnt = g_cntv[pos];

    float acc[32];
#pragma unroll
    for (int c = 0; c < 32; c++) acc[c] = 0.f;

    for (int s = 0; s < cnt; s++) {
        int p = g_nbr[s * NPTS + pos];
        int j = p >> 4, tap = p & 15;
        const float4* inr = reinterpret_cast<const float4*>(g_y2 + (size_t)j * 16);
        float4 r0 = inr[0], r1 = inr[1], r2 = inr[2], r3 = inr[3];   // L1-local
        const float* wr = s_ws + tap * 516;       // warp-uniform
        float vv[16] = {r0.x, r0.y, r0.z, r0.w, r1.x, r1.y, r1.z, r1.w,
                        r2.x, r2.y, r2.z, r2.w, r3.x, r3.y, r3.z, r3.w};
#pragma unroll
        for (int ci = 0; ci < 16; ci++) {
            float v = fmaxf(fmaf(vv[ci], s_ab[ci], s_ab[16 + ci]), 0.f);
#pragma unroll
            for (int co = 0; co < 32; co++)
                acc[co] = fmaf(v, wr[ci * 32 + co], acc[co]);
        }
    }

    float4* orow = reinterpret_cast<float4*>(g_y3 + (size_t)pos * 32);
#pragma unroll
    for (int c4 = 0; c4 < 8; c4++)
        orow[c4] = make_float4(acc[4 * c4], acc[4 * c4 + 1], acc[4 * c4 + 2], acc[4 * c4 + 3]);

    block_stats<32>(acc, blockIdx.x);
    LAST_BLOCK_GATE(g_ctr[3], NBLK, s_last);
    if (s_last) fold_bn<32>(g3, b3, g_bn3);
}

// ---------------- 6: BN3+ReLU fused segment-max pool (pos-space) ------------------
__global__ __launch_bounds__(256)
void k_pool() {
    __shared__ unsigned s_p[NB * 32];
    __shared__ float s_ab[64];
    if (threadIdx.x < 64) s_ab[threadIdx.x] = g_bn3[threadIdx.x];
    for (int t = threadIdx.x; t < NB * 32; t += 256) s_p[t] = 0u;
    __syncthreads();

    int pos = blockIdx.x * 256 + threadIdx.x;
    int b = g_src[pos] >> 24;
    const float4* r = reinterpret_cast<const float4*>(g_y3 + (size_t)pos * 32);
#pragma unroll
    for (int c4 = 0; c4 < 8; c4++) {
        float4 t = r[c4];
        float tv[4] = {t.x, t.y, t.z, t.w};
#pragma unroll
        for (int u = 0; u < 4; u++) {
            int c = c4 * 4 + u;
            float v = fmaxf(fmaf(tv[u], s_ab[c], s_ab[32 + c]), 0.f);
            atomicMax(&s_p[b * 32 + c], __float_as_uint(v));   // order-independent
        }
    }
    __syncthreads();
    for (int t = threadIdx.x; t < NB * 32; t += 256) {
        unsigned m = s_p[t];
        if (m) atomicMax(&g_pool[t], m);
    }
}

// ---------------- 7: FC + ReLU; tail-zero state for next replay -------------------
__global__ void k_fc(const float* __restrict__ Wfc, const float* __restrict__ bfc,
                     float* __restrict__ out)
{
    int bb = blockIdx.x, co = threadIdx.x;   // 16 blocks x 128 threads
    __shared__ float p[32];
    if (threadIdx.x < 32) p[threadIdx.x] = __uint_as_float(g_pool[bb * 32 + threadIdx.x]);
    __syncthreads();
    float acc = bfc[co];
#pragma unroll
    for (int ci = 0; ci < 32; ci++)
        acc = fmaf(p[ci], Wfc[ci * 128 + co], acc);
    out[bb * 128 + co] = fmaxf(acc, 0.f);

    // cleanup for next replay (this block's pool region read above; others untouched)
    __syncthreads();
    if (threadIdx.x < 32) g_pool[bb * 32 + threadIdx.x] = 0u;
    int gid = bb * 128 + co;
    for (int t = gid; t < NROWS; t += 2048) { g_rowcnt[t] = 0; g_rowctr[t] = 0; }
    if (gid < 4) g_ctr[gid] = 0u;
}

// ---------------- launch ----------------
extern "C" void kernel_launch(void* const* d_in, const int* in_sizes, int n_in,
                              void* d_out, int out_size)
{
    const float* feats = (const float*)d_in[0];
    const int*   idx   = (const int*)d_in[1];
    const float* W1    = (const float*)d_in[2];
    const float* g1    = (const float*)d_in[3];
    const float* b1    = (const float*)d_in[4];
    const float* W2    = (const float*)d_in[5];
    const float* g2    = (const float*)d_in[6];
    const float* b2    = (const float*)d_in[7];
    const float* W3    = (const float*)d_in[8];
    const float* g3    = (const float*)d_in[9];
    const float* b3    = (const float*)d_in[10];
    const float* Wfc   = (const float*)d_in[11];
    const float* bfc   = (const float*)d_in[12];
    float* out = (float*)d_out;

    k_hist<<<NBLK, 256>>>(idx);                       // 1 (last block: scan)
    k_place<<<NBLK, 256>>>(idx);                      // 2
    k_build<<<NBLK, 256>>>(idx, feats, W1, g1, b1);   // 3
    k_conv2<<<NBLK, 256>>>(W2, g2, b2);               // 4  <- ncu capture
    k_conv3<<<NBLK, 256>>>(W3, g3, b3);               // 5
    k_pool<<<NBLK, 256>>>();                          // 6
    k_fc<<<NB, 128>>>(Wfc, bfc, out);                 // 7 (+ state cleanup)
}

// round 14
// speedup vs baseline: 1.3275x; 1.3275x over previous
#include <cuda_runtime.h>
#include <cstddef>

#define NB    16
#define HH    512
#define WWID  512
#define NPB   20000
#define NPTS  (NB * NPB)          // 320000
#define EPSV  1e-5f
#define NBLK  1250                // NPTS / 256 exactly

// ---------------- scratch ----------------
__device__ int g_map[NB * HH * WWID + 8];          // i+1 encoding; 0 = empty (zero-init; valid across replays)
__device__ int g_nbr[9 * NPTS];                    // i-space tap list (slot-major): (j<<4 | tap)
__device__ int g_cntv[NPTS];
__device__ int g_maskv[NPTS];                      // 9-bit tap mask
__device__ __align__(16) float g_y1[NPTS * 8];
__device__ __align__(16) float g_y2[NPTS * 16];
__device__ __align__(16) float g_y3[NPTS * 32];
__device__ float g_part[NBLK * 64];                // [sum(C) | sumsq(C)] rows, stride 64
__device__ float g_bn1[16], g_bn2[32], g_bn3[64];  // folded scale | shift
__device__ unsigned g_pool[NB * 32];
__device__ unsigned g_ctr[4];

#define LAST_BLOCK_GATE(ctr, target, lastvar)                        \
    __threadfence();                                                 \
    __syncthreads();                                                 \
    if (threadIdx.x == 0)                                            \
        lastvar = (atomicAdd(&(ctr), 1u) == (unsigned)(target) - 1u);\
    __syncthreads();

// ---------------- gated-last-block BN fold ----------------
template <int C>
__device__ __forceinline__ void fold_bn(const float* __restrict__ gamma,
                                        const float* __restrict__ beta,
                                        float* __restrict__ bn) {
    __shared__ float s4[4][64];
    int c = threadIdx.x & 63, seg = threadIdx.x >> 6;
    float a = 0.f;
    if (c < 2 * C && seg < 4)
        for (int r = seg; r < NBLK; r += 4) a += __ldcg(&g_part[r * 64 + c]);
    if (seg < 4) s4[seg][c] = a;
    __syncthreads();
    if ((int)threadIdx.x < C) {
        int c0 = threadIdx.x;
        float S = s4[0][c0] + s4[1][c0] + s4[2][c0] + s4[3][c0];
        float Q = s4[0][C + c0] + s4[1][C + c0] + s4[2][C + c0] + s4[3][C + c0];
        float m = S / (float)NPTS;
        float var = Q / (float)NPTS - m * m;
        float sc = gamma[c0] * rsqrtf(var + EPSV);
        bn[c0] = sc;
        bn[C + c0] = beta[c0] - m * sc;
    }
}

// ---------------- block stats (1 thr/pt): acc[NCH] -> g_part row ----------------
template <int NCH>
__device__ __forceinline__ void block_stats(const float* acc, int blk) {
    __shared__ float s_red[8][2 * NCH];
    int lane = threadIdx.x & 31, warp = threadIdx.x >> 5;
#pragma unroll
    for (int co = 0; co < NCH; co++) {
        float s = acc[co], q = acc[co] * acc[co];
#pragma unroll
        for (int off = 16; off; off >>= 1) {
            s += __shfl_down_sync(0xffffffffu, s, off);
            q += __shfl_down_sync(0xffffffffu, q, off);
        }
        if (lane == 0) { s_red[warp][co] = s; s_red[warp][NCH + co] = q; }
    }
    __syncthreads();
    if (threadIdx.x < 2 * NCH) {
        float t = 0.f;
#pragma unroll
        for (int w = 0; w < 8; w++) t += s_red[w][threadIdx.x];
        g_part[blk * 64 + threadIdx.x] = t;
    }
}

// ---------------- deterministic block-local sort by 9-bit mask (256 pts) ----------
__device__ __forceinline__ void sort_by_mask(int key, unsigned char* wcnt /*8*512*/,
                                             short* tot, short* bb, short* s_ord) {
    int warp = threadIdx.x >> 5, lane = threadIdx.x & 31;
    for (int t = threadIdx.x; t < 8 * 512 / 4; t += 256)
        reinterpret_cast<unsigned*>(wcnt)[t] = 0u;
    __syncthreads();
    unsigned mymask = __match_any_sync(0xffffffffu, key);
    int lrank = __popc(mymask & ((1u << lane) - 1u));
    if (lane == (__ffs(mymask) - 1))
        wcnt[warp * 512 + key] = (unsigned char)__popc(mymask);
    __syncthreads();
    for (int k = threadIdx.x; k < 512; k += 256) {
        int run = 0;
#pragma unroll
        for (int w = 0; w < 8; w++) {
            int c = wcnt[w * 512 + k];
            wcnt[w * 512 + k] = (unsigned char)run;
            run += c;
        }
        tot[k] = (short)run;
    }
    __syncthreads();
    if (threadIdx.x < 32) {
        int l = threadIdx.x;
        int s = 0;
#pragma unroll
        for (int q = 0; q < 16; q++) { bb[l * 16 + q] = (short)s; s += tot[l * 16 + q]; }
        int chunk = s, off = chunk;
#pragma unroll
        for (int d = 1; d < 32; d <<= 1) {
            int n = __shfl_up_sync(0xffffffffu, off, d);
            if (l >= d) off += n;
        }
        off -= chunk;
#pragma unroll
        for (int q = 0; q < 16; q++) bb[l * 16 + q] = (short)(bb[l * 16 + q] + off);
    }
    __syncthreads();
    s_ord[bb[key] + wcnt[warp * 512 + key] + lrank] = (short)threadIdx.x;
    __syncthreads();
}

// ---------------- 1: scatter (i+1) + clear pool/ctr ----------------
__global__ void k_scatter(const int* __restrict__ idx) {
    int i = blockIdx.x * blockDim.x + threadIdx.x;
    if (i < NPTS) {
        int b = idx[3 * i], y = idx[3 * i + 1], x = idx[3 * i + 2];
        g_map[(b << 18) | (y << 9) | x] = i + 1;
    }
    if (i < NB * 32) g_pool[i] = 0u;
    if (i < 4) g_ctr[i] = 0u;
}

// ---------------- 2: probe + conv1 + tap list + mask + stats; gated BN1 fold ------
__global__ __launch_bounds__(256)
void k_build(const int* __restrict__ idx, const float* __restrict__ feats,
             const float* __restrict__ w1,
             const float* __restrict__ g1, const float* __restrict__ b1)
{
    __shared__ float ws[72];
    __shared__ bool s_last;
    if (threadIdx.x < 72) ws[threadIdx.x] = w1[threadIdx.x];
    __syncthreads();

    int i = blockIdx.x * 256 + threadIdx.x;
    int b = idx[3 * i], y = idx[3 * i + 1], x = idx[3 * i + 2];
    int base = b << 18;

    int jj[9];
#pragma unroll
    for (int t = 0; t < 9; t++) {
        int ny = y + t / 3 - 1, nx = x + t % 3 - 1;
        bool ok = ((unsigned)ny < (unsigned)HH) && ((unsigned)nx < (unsigned)WWID);
        int nyc = ok ? ny : y, nxc = ok ? nx : x;
        int j = g_map[base + (nyc << 9) + nxc];
        jj[t] = ok ? (j - 1) : -1;
    }

    float acc[8];
#pragma unroll
    for (int c = 0; c < 8; c++) acc[c] = 0.f;
    int cnt = 0, mask = 0;
#pragma unroll
    for (int t = 0; t < 9; t++) {
        if (jj[t] >= 0) {
            g_nbr[cnt * NPTS + i] = (jj[t] << 4) | t;
            cnt++;
            mask |= (1 << t);
            float v = feats[jj[t]];
#pragma unroll
            for (int co = 0; co < 8; co++)
                acc[co] = fmaf(v, ws[t * 8 + co], acc[co]);
        }
    }
    g_cntv[i] = cnt;
    g_maskv[i] = mask;

    float4* orow = reinterpret_cast<float4*>(g_y1 + (size_t)i * 8);
    orow[0] = make_float4(acc[0], acc[1], acc[2], acc[3]);
    orow[1] = make_float4(acc[4], acc[5], acc[6], acc[7]);

    block_stats<8>(acc, blockIdx.x);
    LAST_BLOCK_GATE(g_ctr[0], NBLK, s_last);
    if (s_last) fold_bn<8>(g1, b1, g_bn1);
}

// ---------------- 3: conv2 (8->16), mask-sorted warps, float4 weight LDS ----------
__global__ __launch_bounds__(256, 4)
void k_conv2(const float* __restrict__ w2,
             const float* __restrict__ g2, const float* __restrict__ b2)
{
    __shared__ float s_ws[9 * 132];            // tap stride 132 floats (528B, 16B-aligned)
    __shared__ float s_ab[32];
    __shared__ unsigned char s_wcnt[8 * 512];
    __shared__ short s_tot[512], s_bb[512], s_ord[256];
    __shared__ bool s_last;
    for (int t = threadIdx.x; t < 9 * 128; t += 256)
        s_ws[(t >> 7) * 132 + (t & 127)] = w2[t];
    if (threadIdx.x < 16) s_ab[threadIdx.x] = g_bn1[threadIdx.x];   // scale8|shift8

    int i0 = blockIdx.x * 256 + threadIdx.x;
    int key = g_maskv[i0];
    sort_by_mask(key, s_wcnt, s_tot, s_bb, s_ord);   // includes syncthreads

    int i = blockIdx.x * 256 + s_ord[threadIdx.x];
    int cnt = g_cntv[i];

    float acc[16];
#pragma unroll
    for (int c = 0; c < 16; c++) acc[c] = 0.f;

    for (int s = 0; s < cnt; s++) {
        int p = g_nbr[s * NPTS + i];
        int j = p >> 4, tap = p & 15;
        const float4* inr = reinterpret_cast<const float4*>(g_y1 + (size_t)j * 8);
        float4 r0 = inr[0], r1 = inr[1];
        // warp-uniform float4 weight loads (LDS.128 broadcast)
        const float4* wq = reinterpret_cast<const float4*>(s_ws + tap * 132);
        float vv[8] = {r0.x, r0.y, r0.z, r0.w, r1.x, r1.y, r1.z, r1.w};
#pragma unroll
        for (int ci = 0; ci < 8; ci++) {
            float v = fmaxf(fmaf(vv[ci], s_ab[ci], s_ab[8 + ci]), 0.f);
#pragma unroll
            for (int c4 = 0; c4 < 4; c4++) {
                float4 w4 = wq[ci * 4 + c4];
                acc[c4 * 4 + 0] = fmaf(v, w4.x, acc[c4 * 4 + 0]);
                acc[c4 * 4 + 1] = fmaf(v, w4.y, acc[c4 * 4 + 1]);
                acc[c4 * 4 + 2] = fmaf(v, w4.z, acc[c4 * 4 + 2]);
                acc[c4 * 4 + 3] = fmaf(v, w4.w, acc[c4 * 4 + 3]);
            }
        }
    }

    float4* orow = reinterpret_cast<float4*>(g_y2 + (size_t)i * 16);
#pragma unroll
    for (int c4 = 0; c4 < 4; c4++)
        orow[c4] = make_float4(acc[4 * c4], acc[4 * c4 + 1], acc[4 * c4 + 2], acc[4 * c4 + 3]);

    block_stats<16>(acc, blockIdx.x);
    LAST_BLOCK_GATE(g_ctr[1], NBLK, s_last);
    if (s_last) fold_bn<16>(g2, b2, g_bn2);
}

// ---------------- 4: conv3 (16->32), mask-sorted warps, float4 weight LDS ---------
__global__ __launch_bounds__(256, 3)
void k_conv3(const float* __restrict__ w3,
             const float* __restrict__ g3, const float* __restrict__ b3)
{
    __shared__ float s_ws[9 * 516];            // tap stride 516 floats (2064B, 16B-aligned)
    __shared__ float s_ab[32];
    __shared__ unsigned char s_wcnt[8 * 512];
    __shared__ short s_tot[512], s_bb[512], s_ord[256];
    __shared__ bool s_last;
    for (int t = threadIdx.x; t < 9 * 512; t += 256)
        s_ws[(t >> 9) * 516 + (t & 511)] = w3[t];
    if (threadIdx.x < 32) s_ab[threadIdx.x] = g_bn2[threadIdx.x];   // scale16|shift16

    int i0 = blockIdx.x * 256 + threadIdx.x;
    int key = g_maskv[i0];
    sort_by_mask(key, s_wcnt, s_tot, s_bb, s_ord);

    int i = blockIdx.x * 256 + s_ord[threadIdx.x];
    int cnt = g_cntv[i];

    float acc[32];
#pragma unroll
    for (int c = 0; c < 32; c++) acc[c] = 0.f;

    for (int s = 0; s < cnt; s++) {
        int p = g_nbr[s * NPTS + i];
        int j = p >> 4, tap = p & 15;
        const float4* inr = reinterpret_cast<const float4*>(g_y2 + (size_t)j * 16);
        float4 r0 = inr[0], r1 = inr[1], r2 = inr[2], r3 = inr[3];
        // warp-uniform float4 weight loads (LDS.128 broadcast)
        const float4* wq = reinterpret_cast<const float4*>(s_ws + tap * 516);
        float vv[16] = {r0.x, r0.y, r0.z, r0.w, r1.x, r1.y, r1.z, r1.w,
                        r2.x, r2.y, r2.z, r2.w, r3.x, r3.y, r3.z, r3.w};
#pragma unroll
        for (int ci = 0; ci < 16; ci++) {
            float v = fmaxf(fmaf(vv[ci], s_ab[ci], s_ab[16 + ci]), 0.f);
#pragma unroll
            for (int c4 = 0; c4 < 8; c4++) {
                float4 w4 = wq[ci * 8 + c4];
                acc[c4 * 4 + 0] = fmaf(v, w4.x, acc[c4 * 4 + 0]);
                acc[c4 * 4 + 1] = fmaf(v, w4.y, acc[c4 * 4 + 1]);
                acc[c4 * 4 + 2] = fmaf(v, w4.z, acc[c4 * 4 + 2]);
                acc[c4 * 4 + 3] = fmaf(v, w4.w, acc[c4 * 4 + 3]);
            }
        }
    }

    float4* orow = reinterpret_cast<float4*>(g_y3 + (size_t)i * 32);
#pragma unroll
    for (int c4 = 0; c4 < 8; c4++)
        orow[c4] = make_float4(acc[4 * c4], acc[4 * c4 + 1], acc[4 * c4 + 2], acc[4 * c4 + 3]);

    block_stats<32>(acc, blockIdx.x);
    LAST_BLOCK_GATE(g_ctr[2], NBLK, s_last);
    if (s_last) fold_bn<32>(g3, b3, g_bn3);
}

// ---------------- 5: BN3+ReLU fused segment-max pool ----------------
__global__ void k_pool(const int* __restrict__ idx) {
    int bb = blockIdx.y;
    int l = blockIdx.x * 256 + threadIdx.x;
    __shared__ float s_ab[64];
    if (threadIdx.x < 64) s_ab[threadIdx.x] = g_bn3[threadIdx.x];
    __syncthreads();
    float v[32];
#pragma unroll
    for (int c = 0; c < 32; c++) v[c] = 0.f;
    if (l < NPB) {
        int i = bb * NPB + l;
        const float4* r = reinterpret_cast<const float4*>(g_y3 + (size_t)i * 32);
#pragma unroll
        for (int c4 = 0; c4 < 8; c4++) {
            float4 t = r[c4];
            float tv[4] = {t.x, t.y, t.z, t.w};
#pragma unroll
            for (int u = 0; u < 4; u++) {
                int c = c4 * 4 + u;
                v[c] = fmaxf(fmaf(tv[u], s_ab[c], s_ab[32 + c]), 0.f);
            }
        }
    }
    __shared__ float red[8][32];
    int lane = threadIdx.x & 31, wid = threadIdx.x >> 5;
#pragma unroll
    for (int c = 0; c < 32; c++) {
        float m = v[c];
#pragma unroll
        for (int off = 16; off; off >>= 1)
            m = fmaxf(m, __shfl_down_sync(0xffffffffu, m, off));
        if (lane == 0) red[wid][c] = m;
    }
    __syncthreads();
    if (threadIdx.x < 32) {
        float m = 0.f;
#pragma unroll
        for (int wdx = 0; wdx < 8; wdx++) m = fmaxf(m, red[wdx][threadIdx.x]);
        atomicMax(&g_pool[bb * 32 + threadIdx.x], __float_as_uint(m));
    }
}

// ---------------- 6: FC + ReLU ----------------
__global__ void k_fc(const float* __restrict__ Wfc, const float* __restrict__ bfc,
                     float* __restrict__ out)
{
    int bb = blockIdx.x, co = threadIdx.x;
    __shared__ float p[32];
    if (threadIdx.x < 32) p[threadIdx.x] = __uint_as_float(g_pool[bb * 32 + threadIdx.x]);
    __syncthreads();
    float acc = bfc[co];
#pragma unroll
    for (int ci = 0; ci < 32; ci++)
        acc = fmaf(p[ci], Wfc[ci * 128 + co], acc);
    out[bb * 128 + co] = fmaxf(acc, 0.f);
}

// ---------------- launch ----------------
extern "C" void kernel_launch(void* const* d_in, const int* in_sizes, int n_in,
                              void* d_out, int out_size)
{
    const float* feats = (const float*)d_in[0];
    const int*   idx   = (const int*)d_in[1];
    const float* W1    = (const float*)d_in[2];
    const float* g1    = (const float*)d_in[3];
    const float* b1    = (const float*)d_in[4];
    const float* W2    = (const float*)d_in[5];
    const float* g2    = (const float*)d_in[6];
    const float* b2    = (const float*)d_in[7];
    const float* W3    = (const float*)d_in[8];
    const float* g3    = (const float*)d_in[9];
    const float* b3    = (const float*)d_in[10];
    const float* Wfc   = (const float*)d_in[11];
    const float* bfc   = (const float*)d_in[12];
    float* out = (float*)d_out;

    k_scatter<<<NBLK, 256>>>(idx);                    // 1
    k_build<<<NBLK, 256>>>(idx, feats, W1, g1, b1);   // 2
    k_conv2<<<NBLK, 256>>>(W2, g2, b2);               // 3
    k_conv3<<<NBLK, 256>>>(W3, g3, b3);               // 4  <- ncu capture
    dim3 pg((NPB + 255) / 256, NB);
    k_pool<<<pg, 256>>>(idx);                         // 5
    k_fc<<<NB, 128>>>(Wfc, bfc, out);                 // 6
}